// round 9
// baseline (speedup 1.0000x reference)
#include <cuda_runtime.h>

#define BATCH   8192
#define KDIM    256
#define EPSF    1e-10f
#define SW8     4
#define SW4     3

// Packed fp32x2 ops (Blackwell): only reachable via PTX.
#define FMA_F32X2(d, a, b, c) \
    asm("fma.rn.f32x2 %0, %1, %2, %3;" : "=l"(d) : "l"(a), "l"(b), "l"(c))
#define ADD_F32X2(d, a, b) \
    asm("add.rn.f32x2 %0, %1, %2;" : "=l"(d) : "l"(a), "l"(b))
#define UNPACK_F32X2(lo, hi, in) do {                                   \
    unsigned _ulo, _uhi;                                                \
    asm("mov.b64 {%0, %1}, %2;" : "=r"(_ulo), "=r"(_uhi) : "l"(in));    \
    lo = __uint_as_float(_ulo); hi = __uint_as_float(_uhi);             \
} while (0)

// Scratch, element-major [BATCH][96]:
// 0..63  -> M8[i][j] = dot(row i,   row 8+j)   (o = i*8+j)
// 64..79 -> ML[i][j] = dot(row i,   row 4+j)
// 80..95 -> MR[i][j] = dot(row 8+i, row 12+j)
__device__ float g_scratch[BATCH * 96];

// ---------------------------------------------------------------------------
// Kernel 1: cross-Gram blocks. One CTA/element (R7 structure: best measured).
// Packed f32x2 accumulate AND packed tree reduce (saves the unpack block).
// ---------------------------------------------------------------------------
__global__ __launch_bounds__(128)
void gram_kernel(const float* __restrict__ sites) {
    const int b    = blockIdx.x;
    const int tid  = threadIdx.x;
    const int warp = tid >> 5;
    const int lane = tid & 31;

    // Row r = 256 floats = 64 x 16B. Lane owns chunks (lane) and (lane+32).
    const ulonglong2* S2 = (const ulonglong2*)(sites + (size_t)b * (16 * KDIM));

    if (warp < 2) {
        // M8 rows i = warp*4..warp*4+3 vs rows 8..15 -> 32 outputs
        ulonglong2 Ar[4][2];
        #pragma unroll
        for (int a = 0; a < 4; a++) {
            Ar[a][0] = S2[(warp * 4 + a) * 64 + lane];
            Ar[a][1] = S2[(warp * 4 + a) * 64 + lane + 32];
        }
        unsigned long long acc[32];
        #pragma unroll
        for (int o = 0; o < 32; o++) acc[o] = 0ull;  // (0.f,0.f)

        #pragma unroll
        for (int j = 0; j < 8; j++) {
            ulonglong2 B0 = S2[(8 + j) * 64 + lane];
            ulonglong2 B1 = S2[(8 + j) * 64 + lane + 32];
            #pragma unroll
            for (int a = 0; a < 4; a++) {
                unsigned long long& d = acc[a * 8 + j];
                FMA_F32X2(d, Ar[a][0].x, B0.x, d);
                FMA_F32X2(d, Ar[a][0].y, B0.y, d);
                FMA_F32X2(d, Ar[a][1].x, B1.x, d);
                FMA_F32X2(d, Ar[a][1].y, B1.y, d);
            }
        }
        // Packed multi-value tree reduce: lane l ends with output l in acc[0].
        #pragma unroll
        for (int stride = 16; stride >= 1; stride >>= 1) {
            #pragma unroll
            for (int j = 0; j < stride; j++) {
                unsigned long long send = (lane & stride) ? acc[j] : acc[j + stride];
                unsigned long long recv = __shfl_xor_sync(0xffffffffu, send, stride);
                unsigned long long keep = (lane & stride) ? acc[j + stride] : acc[j];
                ADD_F32X2(acc[j], keep, recv);
            }
        }
        float lo, hi; UNPACK_F32X2(lo, hi, acc[0]);
        g_scratch[b * 96 + warp * 32 + lane] = lo + hi;
    } else {
        // warp2: ML (rows 0-3 x 4-7); warp3: MR (rows 8-11 x 12-15) -> 16 outputs
        const int ra   = (warp == 2) ? 0 : 8;
        const int base = (warp == 2) ? 64 : 80;
        ulonglong2 Ar[4][2];
        #pragma unroll
        for (int a = 0; a < 4; a++) {
            Ar[a][0] = S2[(ra + a) * 64 + lane];
            Ar[a][1] = S2[(ra + a) * 64 + lane + 32];
        }
        unsigned long long acc[16];
        #pragma unroll
        for (int o = 0; o < 16; o++) acc[o] = 0ull;

        #pragma unroll
        for (int j = 0; j < 4; j++) {
            ulonglong2 B0 = S2[(ra + 4 + j) * 64 + lane];
            ulonglong2 B1 = S2[(ra + 4 + j) * 64 + lane + 32];
            #pragma unroll
            for (int a = 0; a < 4; a++) {
                unsigned long long& d = acc[a * 4 + j];
                FMA_F32X2(d, Ar[a][0].x, B0.x, d);
                FMA_F32X2(d, Ar[a][0].y, B0.y, d);
                FMA_F32X2(d, Ar[a][1].x, B1.x, d);
                FMA_F32X2(d, Ar[a][1].y, B1.y, d);
            }
        }
        // Fold upper 16 lanes (packed), then 15-step packed tree over 16 values.
        #pragma unroll
        for (int j = 0; j < 16; j++) {
            unsigned long long r16 = __shfl_xor_sync(0xffffffffu, acc[j], 16);
            ADD_F32X2(acc[j], acc[j], r16);
        }
        #pragma unroll
        for (int stride = 8; stride >= 1; stride >>= 1) {
            #pragma unroll
            for (int j = 0; j < stride; j++) {
                unsigned long long send = (lane & stride) ? acc[j] : acc[j + stride];
                unsigned long long recv = __shfl_xor_sync(0xffffffffu, send, stride);
                unsigned long long keep = (lane & stride) ? acc[j + stride] : acc[j];
                ADD_F32X2(acc[j], keep, recv);
            }
        }
        if (lane < 16) {
            float lo, hi; UNPACK_F32X2(lo, hi, acc[0]);
            g_scratch[b * 96 + base + lane] = lo + hi;
        }
    }
}

// ---------------------------------------------------------------------------
// Kernel 2: 8 lanes per element; one column per lane (one-sided Jacobi).
// 8x8 rounds and 4x4 rounds INTERLEAVED in one loop: two independent
// dependency chains per iteration for the scheduler to overlap.
// ---------------------------------------------------------------------------
__device__ __forceinline__ void rot_params(float al, float be, float ga,
                                           float& c, float& s) {
    float tau = (be - al) * __fdividef(0.5f, ga);
    float t = copysignf(1.f, tau) *
              __fdividef(1.f, fabsf(tau) + sqrtf(fmaf(tau, tau, 1.f)));
    t = (fabsf(ga) > 1e-30f) ? t : 0.f;
    c = rsqrtf(fmaf(t, t, 1.f));
    s = c * t;
}

__global__ __launch_bounds__(128)
void jacobi_kernel(float* __restrict__ out) {
    const unsigned FULL = 0xffffffffu;
    const int tid = threadIdx.x;
    const int j   = tid & 7;                        // my column (8x8)
    const int b   = blockIdx.x * 16 + (tid >> 3);   // element
    const float* base = g_scratch + b * 96;

    // Load both problems upfront.
    float a[8];
    #pragma unroll
    for (int k = 0; k < 8; k++) a[k] = base[k * 8 + j];

    const int j4  = j & 3;
    const int isR = j >> 2;                         // lanes 0-3 -> ML, 4-7 -> MR
    const float* mb = base + 64 + isR * 16;
    float m4[4];
    #pragma unroll
    for (int k = 0; k < 4; k++) m4[k] = mb[k * 4 + j4];

    // Merged loop: 28 rounds of 8x8 (4 sweeps x 7), with the 9 rounds of the
    // 4x4s (3 sweeps x 3) piggybacked on iterations 0..8. Chains independent.
    #pragma unroll 1
    for (int rr = 0; rr < SW8 * 7; rr++) {
        const int r = rr % 7;
        // --- 8x8 round ---
        int partner = (j == r) ? 7 : ((j == 7) ? r : ((2 * r + 14 - j) % 7));
        float n = 0.f;
        #pragma unroll
        for (int k = 0; k < 8; k++) n = fmaf(a[k], a[k], n);
        float bc[8];
        #pragma unroll
        for (int k = 0; k < 8; k++) bc[k] = __shfl_sync(FULL, a[k], partner, 8);
        float bn = __shfl_sync(FULL, n, partner, 8);
        float ga = 0.f;
        #pragma unroll
        for (int k = 0; k < 8; k++) ga = fmaf(a[k], bc[k], ga);
        float c, s;
        rot_params(n, bn, ga, c, s);
        #pragma unroll
        for (int k = 0; k < 8; k++) a[k] = fmaf(c, a[k], -s * bc[k]);

        // --- 4x4 round (first 9 iterations only) ---
        if (rr < SW4 * 3) {
            const int r4 = rr % 3;
            int p4 = (j4 == r4) ? 3 : ((j4 == 3) ? r4 : ((2 * r4 + 6 - j4) % 3));
            float n4 = 0.f;
            #pragma unroll
            for (int k = 0; k < 4; k++) n4 = fmaf(m4[k], m4[k], n4);
            float bc4[4];
            #pragma unroll
            for (int k = 0; k < 4; k++) bc4[k] = __shfl_sync(FULL, m4[k], p4, 4);
            float bn4 = __shfl_sync(FULL, n4, p4, 4);
            float ga4 = 0.f;
            #pragma unroll
            for (int k = 0; k < 4; k++) ga4 = fmaf(m4[k], bc4[k], ga4);
            float c4, s4p;
            rot_params(n4, bn4, ga4, c4, s4p);
            #pragma unroll
            for (int k = 0; k < 4; k++) m4[k] = fmaf(c4, m4[k], -s4p * bc4[k]);
        }
    }

    // ---- entropies ----
    float sq8 = EPSF;
    #pragma unroll
    for (int k = 0; k < 8; k++) sq8 = fmaf(a[k], a[k], sq8);
    float T8 = sq8;
    #pragma unroll
    for (int m = 4; m >= 1; m >>= 1) T8 += __shfl_xor_sync(FULL, T8, m, 8);
    float p8 = sq8 * __fdividef(1.f, T8);
    float s8 = p8 * __logf(p8 + EPSF);
    #pragma unroll
    for (int m = 4; m >= 1; m >>= 1) s8 += __shfl_xor_sync(FULL, s8, m, 8);
    // S_whole = -s8 (all 8 lanes agree)

    float sq4 = EPSF;
    #pragma unroll
    for (int k = 0; k < 4; k++) sq4 = fmaf(m4[k], m4[k], sq4);
    float T4 = sq4;
    #pragma unroll
    for (int m = 2; m >= 1; m >>= 1) T4 += __shfl_xor_sync(FULL, T4, m, 4);
    float p4v = sq4 * __fdividef(1.f, T4);
    float s4 = p4v * __logf(p4v + EPSF);
    #pragma unroll
    for (int m = 2; m >= 1; m >>= 1) s4 += __shfl_xor_sync(FULL, s4, m, 4);
    // lanes 0-3 hold sum for ML, lanes 4-7 for MR

    float s4R = __shfl_sync(FULL, s4, 4, 8);   // lane 0 reads MR's sum from lane 4
    if (j == 0) {
        // phi = S_whole - S_left - S_right = -s8 + s4(L) + s4(R)
        float phi = -s8 + s4 + s4R;
        out[b] = phi > 0.f ? phi : 0.f;
    }
}

extern "C" void kernel_launch(void* const* d_in, const int* in_sizes, int n_in,
                              void* d_out, int out_size) {
    const float* sites = (const float*)d_in[0];
    float* out = (float*)d_out;
    gram_kernel<<<BATCH, 128>>>(sites);
    jacobi_kernel<<<BATCH / 16, 128>>>(out);
}

// round 10
// speedup vs baseline: 1.2070x; 1.2070x over previous
#include <cuda_runtime.h>

#define BATCH   8192
#define KDIM    256
#define EPSF    1e-10f
#define SW8     4
#define SW4     3

// Packed fp32x2 ops (Blackwell): only reachable via PTX.
#define FMA_F32X2(d, a, b, c) \
    asm("fma.rn.f32x2 %0, %1, %2, %3;" : "=l"(d) : "l"(a), "l"(b), "l"(c))
#define MUL_F32X2(d, a, b) \
    asm("mul.rn.f32x2 %0, %1, %2;" : "=l"(d) : "l"(a), "l"(b))
#define UNPACK_F32X2(lo, hi, in) do {                                   \
    unsigned _ulo, _uhi;                                                \
    asm("mov.b64 {%0, %1}, %2;" : "=r"(_ulo), "=r"(_uhi) : "l"(in));    \
    lo = __uint_as_float(_ulo); hi = __uint_as_float(_uhi);             \
} while (0)

// Scratch, element-major [BATCH][96]:
// 0..63  -> M8[i][j] = dot(row i,   row 8+j)   (o = i*8+j)
// 64..79 -> ML[i][j] = dot(row i,   row 4+j)
// 80..95 -> MR[i][j] = dot(row 8+i, row 12+j)
__device__ float g_scratch[BATCH * 96];

// ---------------------------------------------------------------------------
// Kernel 1: cross-Gram blocks. One CTA/element, direct LDG.128, f32x2 FMAs,
// scalar 31-shfl tree (R7 proven-best). Accumulators MUL-initialized on their
// first chunk (no zero block).
// ---------------------------------------------------------------------------
__global__ __launch_bounds__(128)
void gram_kernel(const float* __restrict__ sites) {
    const int b    = blockIdx.x;
    const int tid  = threadIdx.x;
    const int warp = tid >> 5;
    const int lane = tid & 31;

    // Row r = 256 floats = 64 x 16B. Lane owns chunks (lane) and (lane+32).
    const ulonglong2* S2 = (const ulonglong2*)(sites + (size_t)b * (16 * KDIM));

    if (warp < 2) {
        // M8 rows i = warp*4..warp*4+3 vs rows 8..15 -> 32 outputs
        ulonglong2 Ar[4][2];
        #pragma unroll
        for (int a = 0; a < 4; a++) {
            Ar[a][0] = S2[(warp * 4 + a) * 64 + lane];
            Ar[a][1] = S2[(warp * 4 + a) * 64 + lane + 32];
        }
        unsigned long long acc[32];
        #pragma unroll
        for (int j = 0; j < 8; j++) {
            ulonglong2 B0 = S2[(8 + j) * 64 + lane];
            ulonglong2 B1 = S2[(8 + j) * 64 + lane + 32];
            #pragma unroll
            for (int a = 0; a < 4; a++) {
                unsigned long long& d = acc[a * 8 + j];
                MUL_F32X2(d, Ar[a][0].x, B0.x);
                FMA_F32X2(d, Ar[a][0].y, B0.y, d);
                FMA_F32X2(d, Ar[a][1].x, B1.x, d);
                FMA_F32X2(d, Ar[a][1].y, B1.y, d);
            }
        }
        float v[32];
        #pragma unroll
        for (int o = 0; o < 32; o++) {
            float lo, hi; UNPACK_F32X2(lo, hi, acc[o]);
            v[o] = lo + hi;
        }
        // Multi-value tree reduce: 32 lane-sums in 31 shfl; lane l ends with out l.
        #pragma unroll
        for (int stride = 16; stride >= 1; stride >>= 1) {
            #pragma unroll
            for (int j = 0; j < stride; j++) {
                float send = (lane & stride) ? v[j] : v[j + stride];
                float recv = __shfl_xor_sync(0xffffffffu, send, stride);
                v[j] = ((lane & stride) ? v[j + stride] : v[j]) + recv;
            }
        }
        g_scratch[b * 96 + warp * 32 + lane] = v[0];
    } else {
        // warp2: ML (rows 0-3 x 4-7); warp3: MR (rows 8-11 x 12-15) -> 16 outputs
        const int ra   = (warp == 2) ? 0 : 8;
        const int base = (warp == 2) ? 64 : 80;
        ulonglong2 Ar[4][2];
        #pragma unroll
        for (int a = 0; a < 4; a++) {
            Ar[a][0] = S2[(ra + a) * 64 + lane];
            Ar[a][1] = S2[(ra + a) * 64 + lane + 32];
        }
        unsigned long long acc[16];
        #pragma unroll
        for (int j = 0; j < 4; j++) {
            ulonglong2 B0 = S2[(ra + 4 + j) * 64 + lane];
            ulonglong2 B1 = S2[(ra + 4 + j) * 64 + lane + 32];
            #pragma unroll
            for (int a = 0; a < 4; a++) {
                unsigned long long& d = acc[a * 4 + j];
                MUL_F32X2(d, Ar[a][0].x, B0.x);
                FMA_F32X2(d, Ar[a][0].y, B0.y, d);
                FMA_F32X2(d, Ar[a][1].x, B1.x, d);
                FMA_F32X2(d, Ar[a][1].y, B1.y, d);
            }
        }
        float v[16];
        #pragma unroll
        for (int o = 0; o < 16; o++) {
            float lo, hi; UNPACK_F32X2(lo, hi, acc[o]);
            v[o] = lo + hi;
        }
        #pragma unroll
        for (int j = 0; j < 16; j++) v[j] += __shfl_xor_sync(0xffffffffu, v[j], 16);
        #pragma unroll
        for (int stride = 8; stride >= 1; stride >>= 1) {
            #pragma unroll
            for (int j = 0; j < stride; j++) {
                float send = (lane & stride) ? v[j] : v[j + stride];
                float recv = __shfl_xor_sync(0xffffffffu, send, stride);
                v[j] = ((lane & stride) ? v[j + stride] : v[j]) + recv;
            }
        }
        if (lane < 16) g_scratch[b * 96 + base + lane] = v[0];
    }
}

// ---------------------------------------------------------------------------
// Kernel 2: 8 lanes per element; one column per lane (one-sided Jacobi).
// R7 structure + partner indices hoisted out of the sweep loop + 2-way
// split of the norm/gamma accumulation chains.
// ---------------------------------------------------------------------------
__device__ __forceinline__ void rot_params(float al, float be, float ga,
                                           float& c, float& s) {
    float tau = (be - al) * __fdividef(0.5f, ga);
    float t = copysignf(1.f, tau) *
              __fdividef(1.f, fabsf(tau) + sqrtf(fmaf(tau, tau, 1.f)));
    t = (fabsf(ga) > 1e-30f) ? t : 0.f;
    c = rsqrtf(fmaf(t, t, 1.f));
    s = c * t;
}

__global__ __launch_bounds__(128)
void jacobi_kernel(float* __restrict__ out) {
    const unsigned FULL = 0xffffffffu;
    const int tid = threadIdx.x;
    const int j   = tid & 7;                        // my column (8x8)
    const int b   = blockIdx.x * 16 + (tid >> 3);   // element
    const float* base = g_scratch + b * 96;

    // ---- 8x8 ----
    float a[8];
    #pragma unroll
    for (int k = 0; k < 8; k++) a[k] = base[k * 8 + j];

    // Partner for each round r, computed once (depends only on r and lane).
    int prt8[7];
    #pragma unroll
    for (int r = 0; r < 7; r++)
        prt8[r] = (j == r) ? 7 : ((j == 7) ? r : ((2 * r + 14 - j) % 7));

    #pragma unroll 1
    for (int sw = 0; sw < SW8; sw++) {
        #pragma unroll
        for (int r = 0; r < 7; r++) {
            const int partner = prt8[r];
            float n0 = 0.f, n1 = 0.f;
            #pragma unroll
            for (int k = 0; k < 4; k++) n0 = fmaf(a[k], a[k], n0);
            #pragma unroll
            for (int k = 4; k < 8; k++) n1 = fmaf(a[k], a[k], n1);
            float n = n0 + n1;
            float bc[8];
            #pragma unroll
            for (int k = 0; k < 8; k++) bc[k] = __shfl_sync(FULL, a[k], partner, 8);
            float bn = __shfl_sync(FULL, n, partner, 8);
            float g0 = 0.f, g1 = 0.f;
            #pragma unroll
            for (int k = 0; k < 4; k++) g0 = fmaf(a[k], bc[k], g0);
            #pragma unroll
            for (int k = 4; k < 8; k++) g1 = fmaf(a[k], bc[k], g1);
            float ga = g0 + g1;
            float c, s;
            rot_params(n, bn, ga, c, s);
            #pragma unroll
            for (int k = 0; k < 8; k++) a[k] = fmaf(c, a[k], -s * bc[k]);
        }
    }
    // entropy of column norms^2
    float sq8 = EPSF;
    #pragma unroll
    for (int k = 0; k < 8; k++) sq8 = fmaf(a[k], a[k], sq8);
    float T8 = sq8;
    #pragma unroll
    for (int m = 4; m >= 1; m >>= 1) T8 += __shfl_xor_sync(FULL, T8, m, 8);
    float p8 = sq8 * __fdividef(1.f, T8);
    float s8 = p8 * __logf(p8 + EPSF);
    #pragma unroll
    for (int m = 4; m >= 1; m >>= 1) s8 += __shfl_xor_sync(FULL, s8, m, 8);
    // S_whole = -s8 (all 8 lanes agree)

    // ---- both 4x4s: lanes 0-3 -> ML, lanes 4-7 -> MR, width-4 shuffles ----
    const int j4  = j & 3;
    const int isR = j >> 2;
    const float* mb = base + 64 + isR * 16;
    float m4[4];
    #pragma unroll
    for (int k = 0; k < 4; k++) m4[k] = mb[k * 4 + j4];

    int prt4[3];
    #pragma unroll
    for (int r = 0; r < 3; r++)
        prt4[r] = (j4 == r) ? 3 : ((j4 == 3) ? r : ((2 * r + 6 - j4) % 3));

    #pragma unroll 1
    for (int sw = 0; sw < SW4; sw++) {
        #pragma unroll
        for (int r = 0; r < 3; r++) {
            const int partner = prt4[r];
            float n0 = 0.f, n1 = 0.f;
            n0 = fmaf(m4[0], m4[0], n0); n0 = fmaf(m4[1], m4[1], n0);
            n1 = fmaf(m4[2], m4[2], n1); n1 = fmaf(m4[3], m4[3], n1);
            float n = n0 + n1;
            float bc[4];
            #pragma unroll
            for (int k = 0; k < 4; k++) bc[k] = __shfl_sync(FULL, m4[k], partner, 4);
            float bn = __shfl_sync(FULL, n, partner, 4);
            float g0 = fmaf(m4[0], bc[0], 0.f); g0 = fmaf(m4[1], bc[1], g0);
            float g1 = fmaf(m4[2], bc[2], 0.f); g1 = fmaf(m4[3], bc[3], g1);
            float ga = g0 + g1;
            float c, s;
            rot_params(n, bn, ga, c, s);
            #pragma unroll
            for (int k = 0; k < 4; k++) m4[k] = fmaf(c, m4[k], -s * bc[k]);
        }
    }
    float sq4 = EPSF;
    #pragma unroll
    for (int k = 0; k < 4; k++) sq4 = fmaf(m4[k], m4[k], sq4);
    float T4 = sq4;
    #pragma unroll
    for (int m = 2; m >= 1; m >>= 1) T4 += __shfl_xor_sync(FULL, T4, m, 4);
    float p4 = sq4 * __fdividef(1.f, T4);
    float s4 = p4 * __logf(p4 + EPSF);
    #pragma unroll
    for (int m = 2; m >= 1; m >>= 1) s4 += __shfl_xor_sync(FULL, s4, m, 4);
    // lanes 0-3 hold sum for ML, lanes 4-7 for MR

    float s4R = __shfl_sync(FULL, s4, 4, 8);   // lane 0 reads MR's sum from lane 4
    if (j == 0) {
        // phi = S_whole - S_left - S_right = -s8 + s4(L) + s4(R)
        float phi = -s8 + s4 + s4R;
        out[b] = phi > 0.f ? phi : 0.f;
    }
}

extern "C" void kernel_launch(void* const* d_in, const int* in_sizes, int n_in,
                              void* d_out, int out_size) {
    const float* sites = (const float*)d_in[0];
    float* out = (float*)d_out;
    gram_kernel<<<BATCH, 128>>>(sites);
    jacobi_kernel<<<BATCH / 16, 128>>>(out);
}